// round 1
// baseline (speedup 1.0000x reference)
#include <cuda_runtime.h>
#include <math.h>

#define NND 100000
#define NE  1600000
#define D   128

// Scratch (static device globals — no runtime allocation allowed)
__device__ float g_buf[NND * D];    // g = (A@W)*dis  (also reused as t3 in head)
__device__ float acc_buf[NND * D];  // scatter accumulator (also reused as t4, stride 64)
__device__ float h_buf[NND * D];    // layer activations
__device__ float dis_buf[NND];
__device__ int   deg_buf[NND];

// ---------------- degree / normalization ----------------

__global__ void k_init_deg() {
    int i = blockIdx.x * blockDim.x + threadIdx.x;
    if (i < NND) deg_buf[i] = 1;  // self loop
}

__global__ void k_count_deg(const int* __restrict__ dst) {
    int e = blockIdx.x * blockDim.x + threadIdx.x;
    if (e < NE) atomicAdd(&deg_buf[dst[e]], 1);
}

__global__ void k_dis() {
    int i = blockIdx.x * blockDim.x + threadIdx.x;
    if (i < NND) dis_buf[i] = rsqrtf((float)deg_buf[i]);
}

// ---------------- GEMM: C[M,BN] = A[M,128] @ W[128,BN] (+epilogue) ----------------
// BM=128 rows per block, K chunked by 32 in shared, 256 threads,
// each thread computes TM x TN = 8 x TN register tile.

template <int BN, int TN, bool GCN_MODE>
__global__ __launch_bounds__(256)
void gemm_k128(const float* __restrict__ A,
               const float* __restrict__ W,
               const float* __restrict__ bias,
               const float* __restrict__ dis,
               float* __restrict__ C,
               float* __restrict__ C2,
               int M)
{
    constexpr int BM = 128, K = 128, KC = 32, TM = 8;
    constexpr int TX = BN / TN;              // threads along N (16)
    __shared__ float As[BM * KC];            // 16 KB
    __shared__ float Ws[KC * BN];            // 16 KB (BN=128) / 8 KB (BN=64)

    const int tid  = threadIdx.x;
    const int row0 = blockIdx.x * BM;
    const int tx   = tid % TX;
    const int ty   = tid / TX;

    float acc[TM][TN];
#pragma unroll
    for (int i = 0; i < TM; i++)
#pragma unroll
        for (int j = 0; j < TN; j++) acc[i][j] = 0.0f;

    for (int kc = 0; kc < K; kc += KC) {
        // load A chunk (BM x KC) as float4, zero-pad out-of-range rows
#pragma unroll
        for (int i = tid; i < BM * KC / 4; i += 256) {
            int r  = i / (KC / 4);
            int c4 = i % (KC / 4);
            float4 v = make_float4(0.f, 0.f, 0.f, 0.f);
            if (row0 + r < M)
                v = *(const float4*)(A + (row0 + r) * K + kc + c4 * 4);
            *(float4*)(As + r * KC + c4 * 4) = v;
        }
        // load W chunk (KC x BN)
#pragma unroll
        for (int i = tid; i < KC * BN / 4; i += 256) {
            *(float4*)(Ws + i * 4) = *(const float4*)(W + kc * BN + i * 4);
        }
        __syncthreads();

#pragma unroll 8
        for (int k = 0; k < KC; k++) {
            float a[TM], w[TN];
#pragma unroll
            for (int i = 0; i < TM; i++) a[i] = As[(ty * TM + i) * KC + k];
#pragma unroll
            for (int j = 0; j < TN; j++) w[j] = Ws[k * BN + tx * TN + j];
#pragma unroll
            for (int i = 0; i < TM; i++)
#pragma unroll
                for (int j = 0; j < TN; j++)
                    acc[i][j] = fmaf(a[i], w[j], acc[i][j]);
        }
        __syncthreads();
    }

    // epilogue
#pragma unroll
    for (int i = 0; i < TM; i++) {
        int row = row0 + ty * TM + i;
        if (row >= M) break;
        int cb = tx * TN;
        if (GCN_MODE) {
            float s = dis[row];
#pragma unroll
            for (int j = 0; j < TN; j++) {
                float v = acc[i][j] * s;
                C [row * BN + cb + j] = v;  // g
                C2[row * BN + cb + j] = v;  // acc init (self-loop term)
            }
        } else {
#pragma unroll
            for (int j = 0; j < TN; j++)
                C[row * BN + cb + j] = acc[i][j] + bias[cb + j];
        }
    }
}

// ---------------- edge scatter: acc[dst] += g[src], one warp per edge ----------------

__global__ void k_scatter(const int* __restrict__ src,
                          const int* __restrict__ dst,
                          const float* __restrict__ g,
                          float* __restrict__ acc)
{
    int e    = (blockIdx.x * blockDim.x + threadIdx.x) >> 5;
    int lane = threadIdx.x & 31;
    if (e >= NE) return;
    int s = src[e];
    int d = dst[e];
    float4 v = *(const float4*)(g + s * D + lane * 4);
    float* p = acc + d * D + lane * 4;
    asm volatile("red.global.add.v4.f32 [%0], {%1, %2, %3, %4};"
                 :: "l"(p), "f"(v.x), "f"(v.y), "f"(v.z), "f"(v.w)
                 : "memory");
}

// ---------------- finalize: h = relu(dis[row]*acc + b[col]) ----------------

__global__ void k_finalize(const float* __restrict__ acc,
                           const float* __restrict__ dis,
                           const float* __restrict__ b,
                           float* __restrict__ h)
{
    int i = blockIdx.x * blockDim.x + threadIdx.x;
    if (i >= NND * D) return;
    float v = acc[i] * dis[i >> 7] + b[i & 127];
    h[i] = fmaxf(v, 0.0f);
}

// ---------------- log_softmax over rows of 64, one warp per row ----------------

__global__ void k_logsoftmax(const float* __restrict__ t4, float* __restrict__ out)
{
    int w    = (blockIdx.x * blockDim.x + threadIdx.x) >> 5;
    int lane = threadIdx.x & 31;
    if (w >= NND) return;
    float2 v = *(const float2*)(t4 + w * 64 + lane * 2);
    float m = fmaxf(v.x, v.y);
#pragma unroll
    for (int o = 16; o; o >>= 1) m = fmaxf(m, __shfl_xor_sync(0xFFFFFFFFu, m, o));
    float s = expf(v.x - m) + expf(v.y - m);
#pragma unroll
    for (int o = 16; o; o >>= 1) s += __shfl_xor_sync(0xFFFFFFFFu, s, o);
    float l = m + logf(s);
    float2 r;
    r.x = v.x - l;
    r.y = v.y - l;
    *(float2*)(out + w * 64 + lane * 2) = r;
}

// ---------------- launch ----------------

extern "C" void kernel_launch(void* const* d_in, const int* in_sizes, int n_in,
                              void* d_out, int out_size)
{
    const float* x   = (const float*)d_in[0];
    const int*   ei  = (const int*)d_in[1];
    const int*   src = ei;
    const int*   dst = ei + NE;
    const float* W1  = (const float*)d_in[2];
    const float* b1  = (const float*)d_in[3];
    const float* W2  = (const float*)d_in[4];
    const float* b2  = (const float*)d_in[5];
    const float* Wp1 = (const float*)d_in[6];
    const float* bp1 = (const float*)d_in[7];
    const float* Wp2 = (const float*)d_in[8];
    const float* bp2 = (const float*)d_in[9];
    float* out = (float*)d_out;

    float *g_p, *acc_p, *h_p, *dis_p;
    cudaGetSymbolAddress((void**)&g_p,   g_buf);
    cudaGetSymbolAddress((void**)&acc_p, acc_buf);
    cudaGetSymbolAddress((void**)&h_p,   h_buf);
    cudaGetSymbolAddress((void**)&dis_p, dis_buf);

    const int GEMM_BLOCKS = (NND + 127) / 128;  // 782

    // normalization
    k_init_deg<<<(NND + 255) / 256, 256>>>();
    k_count_deg<<<(NE + 255) / 256, 256>>>(dst);
    k_dis<<<(NND + 255) / 256, 256>>>();

    // ---- GCN layer 1 ----
    gemm_k128<128, 8, true><<<GEMM_BLOCKS, 256>>>(x, W1, nullptr, dis_p, g_p, acc_p, NND);
    k_scatter<<<(NE * 32 + 255) / 256, 256>>>(src, dst, g_p, acc_p);
    k_finalize<<<(NND * D + 255) / 256, 256>>>(acc_p, dis_p, b1, h_p);

    // ---- GCN layer 2 ----
    gemm_k128<128, 8, true><<<GEMM_BLOCKS, 256>>>(h_p, W2, nullptr, dis_p, g_p, acc_p, NND);
    k_scatter<<<(NE * 32 + 255) / 256, 256>>>(src, dst, g_p, acc_p);
    k_finalize<<<(NND * D + 255) / 256, 256>>>(acc_p, dis_p, b2, h_p);

    // ---- MLP head ----
    gemm_k128<128, 8, false><<<GEMM_BLOCKS, 256>>>(h_p, Wp1, bp1, nullptr, g_p, nullptr, NND);
    gemm_k128<64, 4, false><<<GEMM_BLOCKS, 256>>>(g_p, Wp2, bp2, nullptr, acc_p, nullptr, NND);

    // ---- log_softmax ----
    k_logsoftmax<<<(NND * 32 + 255) / 256, 256>>>(acc_p, out);
}

// round 2
// speedup vs baseline: 1.3038x; 1.3038x over previous
#include <cuda_runtime.h>
#include <math.h>

#define NND 100000
#define NE  1600000
#define D   128

// Scratch (static device globals — no runtime allocation allowed)
__device__ float g_buf[NND * D];    // messages g = (A@W)*dis; reused as t3 in head
__device__ float acc_buf[NND * D];  // scatter accumulator
__device__ float dis_buf[NND];
__device__ int   deg_buf[NND];

// ---------------- degree / normalization ----------------

__global__ void k_init_deg() {
    int i = blockIdx.x * blockDim.x + threadIdx.x;
    if (i < NND) deg_buf[i] = 1;  // self loop
}

__global__ void k_count_deg(const int* __restrict__ dst) {
    int e = blockIdx.x * blockDim.x + threadIdx.x;
    if (e < NE) atomicAdd(&deg_buf[dst[e]], 1);
}

__global__ void k_dis() {
    int i = blockIdx.x * blockDim.x + threadIdx.x;
    if (i < NND) dis_buf[i] = rsqrtf((float)deg_buf[i]);
}

// ---------------- GEMM: C[M,BN] = op_A(A)[M,128] @ W[128,BN] + epilogue ----------------
// BM=128 rows/block, 256 threads, thread tile TM x TN = 8 x TN.
// A stored TRANSPOSED in smem (Ast[k][m], padded stride) -> float4 LDS, conflict-free.
//
// A_FUSE: A element = relu(rawA * dis[row] + biasA[col])   (fused GCN finalize)
// EPI 0: GCN  : v = acc*dis[row];  C=v; C2=v   (self-loop init for scatter)
// EPI 1: BIAS : v = acc + biasC[col]; C=v
// EPI 2: LSM  : v = acc + biasC[col]; log_softmax over row (BN=64); C=result

template <int BN, int TN, bool A_FUSE, int EPI>
__global__ __launch_bounds__(256)
void gemm_k128(const float* __restrict__ A,
               const float* __restrict__ W,
               const float* __restrict__ biasA,   // for A_FUSE
               const float* __restrict__ biasC,   // for EPI 1/2
               const float* __restrict__ dis,
               float* __restrict__ C,
               float* __restrict__ C2,
               int M)
{
    constexpr int BM = 128, K = 128, KC = 32, TM = 8;
    constexpr int TX  = BN / TN;          // threads along N
    constexpr int SAP = BM + 4;           // padded Ast stride (conflict-free STS)
    __shared__ float Ast[KC * SAP];       // transposed A chunk
    __shared__ float Ws [KC * BN];        // W chunk

    const int tid  = threadIdx.x;
    const int row0 = blockIdx.x * BM;
    const int tx   = tid % TX;
    const int ty   = tid / TX;

    float acc[TM][TN];
#pragma unroll
    for (int i = 0; i < TM; i++)
#pragma unroll
        for (int j = 0; j < TN; j++) acc[i][j] = 0.0f;

    for (int kc = 0; kc < K; kc += KC) {
        // ---- load A chunk (BM x KC), optional fused finalize, store transposed ----
#pragma unroll
        for (int p = 0; p < (BM * KC / 4) / 256; p++) {
            int i  = tid + p * 256;
            int r  = i / (KC / 4);
            int c4 = i % (KC / 4);
            float4 v = make_float4(0.f, 0.f, 0.f, 0.f);
            int row = row0 + r;
            if (row < M) {
                v = *(const float4*)(A + row * K + kc + c4 * 4);
                if (A_FUSE) {
                    float s = dis[row];
                    float4 b = *(const float4*)(biasA + kc + c4 * 4);
                    v.x = fmaxf(fmaf(v.x, s, b.x), 0.f);
                    v.y = fmaxf(fmaf(v.y, s, b.y), 0.f);
                    v.z = fmaxf(fmaf(v.z, s, b.z), 0.f);
                    v.w = fmaxf(fmaf(v.w, s, b.w), 0.f);
                }
            }
            Ast[(c4 * 4 + 0) * SAP + r] = v.x;
            Ast[(c4 * 4 + 1) * SAP + r] = v.y;
            Ast[(c4 * 4 + 2) * SAP + r] = v.z;
            Ast[(c4 * 4 + 3) * SAP + r] = v.w;
        }
        // ---- load W chunk (KC x BN) ----
#pragma unroll
        for (int p = 0; p < (KC * BN / 4) / 256; p++) {
            int i = tid + p * 256;
            *(float4*)(Ws + i * 4) = *(const float4*)(W + kc * BN + i * 4);
        }
        __syncthreads();

        // ---- compute ----
#pragma unroll 8
        for (int k = 0; k < KC; k++) {
            float a[TM], w[TN];
            *(float4*)(a + 0) = *(const float4*)(Ast + k * SAP + ty * TM + 0);
            *(float4*)(a + 4) = *(const float4*)(Ast + k * SAP + ty * TM + 4);
            *(float4*)(w + 0) = *(const float4*)(Ws + k * BN + tx * TN + 0);
            if (TN == 8)
                *(float4*)(w + 4) = *(const float4*)(Ws + k * BN + tx * TN + 4);
#pragma unroll
            for (int i = 0; i < TM; i++)
#pragma unroll
                for (int j = 0; j < TN; j++)
                    acc[i][j] = fmaf(a[i], w[j], acc[i][j]);
        }
        __syncthreads();
    }

    // ---------------- epilogue ----------------
    if (EPI == 0) {  // GCN: scale by dis, dual store
#pragma unroll
        for (int i = 0; i < TM; i++) {
            int row = row0 + ty * TM + i;
            if (row >= M) break;
            float s = dis[row];
            int base = row * BN + tx * TN;
#pragma unroll
            for (int j4 = 0; j4 < TN; j4 += 4) {
                float4 v;
                v.x = acc[i][j4 + 0] * s; v.y = acc[i][j4 + 1] * s;
                v.z = acc[i][j4 + 2] * s; v.w = acc[i][j4 + 3] * s;
                *(float4*)(C  + base + j4) = v;
                *(float4*)(C2 + base + j4) = v;
            }
        }
    } else if (EPI == 1) {  // plain bias
#pragma unroll
        for (int i = 0; i < TM; i++) {
            int row = row0 + ty * TM + i;
            if (row >= M) break;
            int base = row * BN + tx * TN;
#pragma unroll
            for (int j4 = 0; j4 < TN; j4 += 4) {
                float4 b = *(const float4*)(biasC + tx * TN + j4);
                float4 v;
                v.x = acc[i][j4 + 0] + b.x; v.y = acc[i][j4 + 1] + b.y;
                v.z = acc[i][j4 + 2] + b.z; v.w = acc[i][j4 + 3] + b.w;
                *(float4*)(C + base + j4) = v;
            }
        }
    } else {  // EPI 2: bias + log_softmax over full row (BN=64, TN=4, TX=16)
        float4 b = *(const float4*)(biasC + tx * TN);
#pragma unroll
        for (int i = 0; i < TM; i++) {
            int row = row0 + ty * TM + i;
            float t[4];
            t[0] = acc[i][0] + b.x; t[1] = acc[i][1] + b.y;
            t[2] = acc[i][2] + b.z; t[3] = acc[i][3] + b.w;
            float m = fmaxf(fmaxf(t[0], t[1]), fmaxf(t[2], t[3]));
#pragma unroll
            for (int o = 8; o; o >>= 1) m = fmaxf(m, __shfl_xor_sync(0xFFFFFFFFu, m, o));
            float s = expf(t[0] - m) + expf(t[1] - m) + expf(t[2] - m) + expf(t[3] - m);
#pragma unroll
            for (int o = 8; o; o >>= 1) s += __shfl_xor_sync(0xFFFFFFFFu, s, o);
            float l = m + logf(s);
            if (row < M) {
                float4 r;
                r.x = t[0] - l; r.y = t[1] - l; r.z = t[2] - l; r.w = t[3] - l;
                *(float4*)(C + row * BN + tx * TN) = r;
            }
        }
    }
}

// ---------------- edge scatter: acc[dst] += g[src], one warp per edge ----------------

__global__ void k_scatter(const int* __restrict__ src,
                          const int* __restrict__ dst,
                          const float* __restrict__ g,
                          float* __restrict__ acc)
{
    int e    = (blockIdx.x * blockDim.x + threadIdx.x) >> 5;
    int lane = threadIdx.x & 31;
    if (e >= NE) return;
    int s = src[e];
    int d = dst[e];
    float4 v = *(const float4*)(g + s * D + lane * 4);
    float* p = acc + d * D + lane * 4;
    asm volatile("red.global.add.v4.f32 [%0], {%1, %2, %3, %4};"
                 :: "l"(p), "f"(v.x), "f"(v.y), "f"(v.z), "f"(v.w)
                 : "memory");
}

// ---------------- launch ----------------

extern "C" void kernel_launch(void* const* d_in, const int* in_sizes, int n_in,
                              void* d_out, int out_size)
{
    const float* x   = (const float*)d_in[0];
    const int*   ei  = (const int*)d_in[1];
    const int*   src = ei;
    const int*   dst = ei + NE;
    const float* W1  = (const float*)d_in[2];
    const float* b1  = (const float*)d_in[3];
    const float* W2  = (const float*)d_in[4];
    const float* b2  = (const float*)d_in[5];
    const float* Wp1 = (const float*)d_in[6];
    const float* bp1 = (const float*)d_in[7];
    const float* Wp2 = (const float*)d_in[8];
    const float* bp2 = (const float*)d_in[9];
    float* out = (float*)d_out;

    float *g_p, *acc_p, *dis_p;
    cudaGetSymbolAddress((void**)&g_p,   g_buf);
    cudaGetSymbolAddress((void**)&acc_p, acc_buf);
    cudaGetSymbolAddress((void**)&dis_p, dis_buf);

    const int GEMM_BLOCKS = (NND + 127) / 128;  // 782

    // normalization
    k_init_deg<<<(NND + 255) / 256, 256>>>();
    k_count_deg<<<(NE + 255) / 256, 256>>>(dst);
    k_dis<<<(NND + 255) / 256, 256>>>();

    // ---- GCN layer 1: g,acc = (x@W1)*dis ; scatter ----
    gemm_k128<128, 8, false, 0><<<GEMM_BLOCKS, 256>>>(
        x, W1, nullptr, nullptr, dis_p, g_p, acc_p, NND);
    k_scatter<<<(NE * 32 + 255) / 256, 256>>>(src, dst, g_p, acc_p);

    // ---- GCN layer 2: A = relu(acc*dis + b1) fused; g,acc = (A@W2)*dis ; scatter ----
    gemm_k128<128, 8, true, 0><<<GEMM_BLOCKS, 256>>>(
        acc_p, W2, b1, nullptr, dis_p, g_p, acc_p, NND);
    k_scatter<<<(NE * 32 + 255) / 256, 256>>>(src, dst, g_p, acc_p);

    // ---- head 1: A = relu(acc*dis + b2) fused; t3 = A@Wp1 + bp1 ----
    gemm_k128<128, 8, true, 1><<<GEMM_BLOCKS, 256>>>(
        acc_p, Wp1, b2, bp1, dis_p, g_p, nullptr, NND);

    // ---- head 2 + log_softmax: out = logsoftmax(t3@Wp2 + bp2) ----
    gemm_k128<64, 4, false, 2><<<GEMM_BLOCKS, 256>>>(
        g_p, Wp2, nullptr, bp2, nullptr, out, nullptr, NND);
}

// round 3
// speedup vs baseline: 2.2543x; 1.7290x over previous
#include <cuda_runtime.h>
#include <math.h>

#define NND 100000
#define NE  1600000
#define D   128

typedef unsigned long long u64;

// Scratch (static device globals — no runtime allocation allowed)
__device__ float g_buf[NND * D];    // messages g = (A@W)*dis; reused as t3 in head
__device__ float acc_buf[NND * D];  // aggregated output per layer
__device__ float dis_buf[NND];
__device__ int   deg_buf[NND];      // in-degree WITHOUT self loop
__device__ int   scan_tmp[NND];
__device__ int   row_ptr[NND + 1];
__device__ int   cursor[NND];
__device__ int   csr_src[NE];
__device__ int   bsum[256];

// ---------------- f32x2 helpers ----------------

__device__ __forceinline__ u64 ffma2(u64 a, u64 b, u64 c) {
    u64 d;
    asm("fma.rn.f32x2 %0, %1, %2, %3;" : "=l"(d) : "l"(a), "l"(b), "l"(c));
    return d;
}
__device__ __forceinline__ u64 pack_dup(float x) {
    u64 r;
    asm("mov.b64 %0, {%1, %1};" : "=l"(r) : "f"(x));
    return r;
}
__device__ __forceinline__ float2 unpack2(u64 v) {
    float2 r;
    asm("mov.b64 {%0, %1}, %2;" : "=f"(r.x), "=f"(r.y) : "l"(v));
    return r;
}

// ---------------- degree / normalization / CSR build ----------------

__global__ void k_init_deg() {
    int i = blockIdx.x * blockDim.x + threadIdx.x;
    if (i < NND) deg_buf[i] = 0;
}

__global__ void k_count_deg(const int* __restrict__ dst) {
    int e = blockIdx.x * blockDim.x + threadIdx.x;
    if (e < NE) atomicAdd(&deg_buf[dst[e]], 1);
}

__global__ void k_dis() {
    int i = blockIdx.x * blockDim.x + threadIdx.x;
    if (i < NND) dis_buf[i] = rsqrtf((float)(deg_buf[i] + 1));
}

#define SCB 512
#define SCAN_BLOCKS ((NND + SCB - 1) / SCB)   // 196

__global__ __launch_bounds__(SCB) void k_scan1() {
    __shared__ int sm[SCB];
    int i = blockIdx.x * SCB + threadIdx.x;
    int v = (i < NND) ? deg_buf[i] : 0;
    sm[threadIdx.x] = v;
    __syncthreads();
#pragma unroll
    for (int off = 1; off < SCB; off <<= 1) {
        int t = (threadIdx.x >= off) ? sm[threadIdx.x - off] : 0;
        __syncthreads();
        sm[threadIdx.x] += t;
        __syncthreads();
    }
    if (i < NND) scan_tmp[i] = sm[threadIdx.x];
    if (threadIdx.x == SCB - 1) bsum[blockIdx.x] = sm[SCB - 1];
}

__global__ __launch_bounds__(256) void k_scan2() {
    __shared__ int sm[256];
    int v = (threadIdx.x < SCAN_BLOCKS) ? bsum[threadIdx.x] : 0;
    sm[threadIdx.x] = v;
    __syncthreads();
#pragma unroll
    for (int off = 1; off < 256; off <<= 1) {
        int t = (threadIdx.x >= off) ? sm[threadIdx.x - off] : 0;
        __syncthreads();
        sm[threadIdx.x] += t;
        __syncthreads();
    }
    bsum[threadIdx.x] = sm[threadIdx.x];  // inclusive
}

__global__ __launch_bounds__(SCB) void k_scan3() {
    int i = blockIdx.x * SCB + threadIdx.x;
    if (i >= NND) return;
    int off = (blockIdx.x > 0) ? bsum[blockIdx.x - 1] : 0;
    int inc = scan_tmp[i] + off;         // inclusive prefix sum of deg
    int st  = inc - deg_buf[i];
    row_ptr[i] = st;
    cursor[i]  = st;
    if (i == NND - 1) row_ptr[NND] = inc;
}

__global__ void k_fill(const int* __restrict__ src, const int* __restrict__ dst) {
    int e = blockIdx.x * blockDim.x + threadIdx.x;
    if (e >= NE) return;
    int p = atomicAdd(&cursor[dst[e]], 1);
    csr_src[p] = src[e];
}

// ---------------- GEMM: C[M,BN] = op_A(A)[M,128] @ W[128,BN] + epilogue ----------------
// BM=128 rows/block, 256 threads, thread tile TM x TN = 8 x TN (TN in {8,4}).
// N-paired f32x2 accumulation: each u64 acc holds 2 adjacent output columns.
// Thread column-pairs are STRIDED (pair p = tx + j*16) so w-fragment LDS.64s are
// lane-consecutive (conflict-free) and Ws smem is a verbatim copy of W's chunk.
//
// A_FUSE: A element = relu(rawA * dis[row] + biasA[col])   (fused GCN finalize)
// EPI 0: GCN  : C = acc * dis[row]          (messages g)
// EPI 1: BIAS : C = acc + biasC[col]
// EPI 2: LSM  : C = log_softmax(acc + biasC[col]) over row (BN=64)

template <int BN, int TN, bool A_FUSE, int EPI>
__global__ __launch_bounds__(256, 2)
void gemm_k128(const float* __restrict__ A,
               const float* __restrict__ W,
               const float* __restrict__ biasA,
               const float* __restrict__ biasC,
               const float* __restrict__ dis,
               float* __restrict__ C,
               int M)
{
    constexpr int BM = 128, K = 128, KC = 32, TM = 8;
    constexpr int TP  = TN / 2;           // u64 pairs per thread
    constexpr int SAP = KC + 4;           // As row stride (keeps float4 16B-aligned)
    __shared__ float As[BM * SAP];
    __shared__ u64   Ws2[KC * BN / 2];

    const int tid  = threadIdx.x;
    const int row0 = blockIdx.x * BM;
    const int tx   = tid & 15;
    const int ty   = tid >> 4;

    u64 acc[TM][TP];
#pragma unroll
    for (int i = 0; i < TM; i++)
#pragma unroll
        for (int j = 0; j < TP; j++) acc[i][j] = 0ULL;

    for (int kc = 0; kc < K; kc += KC) {
        // ---- load A chunk (BM x KC), optional fused finalize ----
#pragma unroll
        for (int p = 0; p < (BM * KC / 4) / 256; p++) {
            int i  = tid + p * 256;
            int r  = i / (KC / 4);
            int c4 = i % (KC / 4);
            float4 v = make_float4(0.f, 0.f, 0.f, 0.f);
            int row = row0 + r;
            if (row < M) {
                v = *(const float4*)(A + row * K + kc + c4 * 4);
                if (A_FUSE) {
                    float s = dis[row];
                    float4 b = *(const float4*)(biasA + kc + c4 * 4);
                    v.x = fmaxf(fmaf(v.x, s, b.x), 0.f);
                    v.y = fmaxf(fmaf(v.y, s, b.y), 0.f);
                    v.z = fmaxf(fmaf(v.z, s, b.z), 0.f);
                    v.w = fmaxf(fmaf(v.w, s, b.w), 0.f);
                }
            }
            *(float4*)(As + r * SAP + c4 * 4) = v;
        }
        // ---- load W chunk (KC x BN) verbatim ----
#pragma unroll
        for (int p = 0; p < (KC * BN / 4) / 256; p++) {
            int i = tid + p * 256;
            ((float4*)Ws2)[i] = *(const float4*)(W + kc * BN + i * 4);
        }
        __syncthreads();

        // ---- compute ----
#pragma unroll 8
        for (int k = 0; k < KC; k++) {
            u64 wp[TP];
#pragma unroll
            for (int j = 0; j < TP; j++)
                wp[j] = Ws2[k * (BN / 2) + j * 16 + tx];
            float a[TM];
#pragma unroll
            for (int i = 0; i < TM; i++)
                a[i] = As[(ty * TM + i) * SAP + k];
            u64 ap[TM];
#pragma unroll
            for (int i = 0; i < TM; i++) ap[i] = pack_dup(a[i]);
#pragma unroll
            for (int i = 0; i < TM; i++)
#pragma unroll
                for (int j = 0; j < TP; j++)
                    acc[i][j] = ffma2(ap[i], wp[j], acc[i][j]);
        }
        __syncthreads();
    }

    // ---------------- epilogue (column pair p=tx+j*16 -> cols 2p, 2p+1) ----------------
    if (EPI == 0) {
#pragma unroll
        for (int i = 0; i < TM; i++) {
            int row = row0 + ty * TM + i;
            if (row >= M) break;
            float s = dis[row];
#pragma unroll
            for (int j = 0; j < TP; j++) {
                float2 v = unpack2(acc[i][j]);
                v.x *= s; v.y *= s;
                *(float2*)(C + row * BN + 2 * (tx + j * 16)) = v;
            }
        }
    } else if (EPI == 1) {
#pragma unroll
        for (int i = 0; i < TM; i++) {
            int row = row0 + ty * TM + i;
            if (row >= M) break;
#pragma unroll
            for (int j = 0; j < TP; j++) {
                float2 b = *(const float2*)(biasC + 2 * (tx + j * 16));
                float2 v = unpack2(acc[i][j]);
                v.x += b.x; v.y += b.y;
                *(float2*)(C + row * BN + 2 * (tx + j * 16)) = v;
            }
        }
    } else {  // EPI 2: BN=64, TP=2, full row across 16 lanes
        float2 b0 = *(const float2*)(biasC + 2 * tx);
        float2 b1 = *(const float2*)(biasC + 2 * (tx + 16));
#pragma unroll
        for (int i = 0; i < TM; i++) {
            int row = row0 + ty * TM + i;
            float2 v0 = unpack2(acc[i][0]);
            float2 v1 = unpack2(acc[i][1]);
            float t0 = v0.x + b0.x, t1 = v0.y + b0.y;
            float t2 = v1.x + b1.x, t3 = v1.y + b1.y;
            float m = fmaxf(fmaxf(t0, t1), fmaxf(t2, t3));
#pragma unroll
            for (int o = 8; o; o >>= 1) m = fmaxf(m, __shfl_xor_sync(0xFFFFFFFFu, m, o));
            float s = expf(t0 - m) + expf(t1 - m) + expf(t2 - m) + expf(t3 - m);
#pragma unroll
            for (int o = 8; o; o >>= 1) s += __shfl_xor_sync(0xFFFFFFFFu, s, o);
            float l = m + logf(s);
            if (row < M) {
                float2 r0, r1;
                r0.x = t0 - l; r0.y = t1 - l;
                r1.x = t2 - l; r1.y = t3 - l;
                *(float2*)(C + row * BN + 2 * tx)        = r0;
                *(float2*)(C + row * BN + 2 * (tx + 16)) = r1;
            }
        }
    }
}

// ---------------- CSR gather: acc[v] = g[v] + sum_{e: dst=v} g[src[e]] ----------------

__global__ __launch_bounds__(256)
void k_gather(const float* __restrict__ g, float* __restrict__ acc)
{
    int node = (blockIdx.x * blockDim.x + threadIdx.x) >> 5;
    int lane = threadIdx.x & 31;
    if (node >= NND) return;
    int beg = row_ptr[node];
    int end = row_ptr[node + 1];
    const float4* gp = (const float4*)g;
    float4 a = gp[node * 32 + lane];  // self-loop term
    for (int e = beg; e < end; e++) {
        int s = __ldg(&csr_src[e]);   // warp-broadcast
        float4 v = gp[s * 32 + lane];
        a.x += v.x; a.y += v.y; a.z += v.z; a.w += v.w;
    }
    ((float4*)acc)[node * 32 + lane] = a;
}

// ---------------- launch ----------------

extern "C" void kernel_launch(void* const* d_in, const int* in_sizes, int n_in,
                              void* d_out, int out_size)
{
    const float* x   = (const float*)d_in[0];
    const int*   ei  = (const int*)d_in[1];
    const int*   src = ei;
    const int*   dst = ei + NE;
    const float* W1  = (const float*)d_in[2];
    const float* b1  = (const float*)d_in[3];
    const float* W2  = (const float*)d_in[4];
    const float* b2  = (const float*)d_in[5];
    const float* Wp1 = (const float*)d_in[6];
    const float* bp1 = (const float*)d_in[7];
    const float* Wp2 = (const float*)d_in[8];
    const float* bp2 = (const float*)d_in[9];
    float* out = (float*)d_out;

    float *g_p, *acc_p, *dis_p;
    cudaGetSymbolAddress((void**)&g_p,   g_buf);
    cudaGetSymbolAddress((void**)&acc_p, acc_buf);
    cudaGetSymbolAddress((void**)&dis_p, dis_buf);

    const int GEMM_BLOCKS   = (NND + 127) / 128;       // 782
    const int GATHER_BLOCKS = (NND * 32 + 255) / 256;  // 12500

    // ---- normalization + CSR build (overlaps nothing; all cheap) ----
    k_init_deg<<<(NND + 255) / 256, 256>>>();
    k_count_deg<<<(NE + 255) / 256, 256>>>(dst);
    k_dis<<<(NND + 255) / 256, 256>>>();
    k_scan1<<<SCAN_BLOCKS, SCB>>>();
    k_scan2<<<1, 256>>>();
    k_scan3<<<SCAN_BLOCKS, SCB>>>();
    k_fill<<<(NE + 255) / 256, 256>>>(src, dst);

    // ---- GCN layer 1: g = (x@W1)*dis ; acc = gather(g) ----
    gemm_k128<128, 8, false, 0><<<GEMM_BLOCKS, 256>>>(
        x, W1, nullptr, nullptr, dis_p, g_p, NND);
    k_gather<<<GATHER_BLOCKS, 256>>>(g_p, acc_p);

    // ---- GCN layer 2: A = relu(acc*dis + b1) fused; g = (A@W2)*dis ; gather ----
    gemm_k128<128, 8, true, 0><<<GEMM_BLOCKS, 256>>>(
        acc_p, W2, b1, nullptr, dis_p, g_p, NND);
    k_gather<<<GATHER_BLOCKS, 256>>>(g_p, acc_p);

    // ---- head 1: A = relu(acc*dis + b2) fused; t3 = A@Wp1 + bp1 ----
    gemm_k128<128, 8, true, 1><<<GEMM_BLOCKS, 256>>>(
        acc_p, Wp1, b2, bp1, dis_p, g_p, NND);

    // ---- head 2 + log_softmax: out = logsoftmax(t3@Wp2 + bp2) ----
    gemm_k128<64, 4, false, 2><<<GEMM_BLOCKS, 256>>>(
        g_p, Wp2, nullptr, bp2, nullptr, out, NND);
}

// round 4
// speedup vs baseline: 2.2582x; 1.0017x over previous
#include <cuda_runtime.h>
#include <math.h>

#define NND 100000
#define NE  1600000
#define D   128

typedef unsigned long long u64;

// Scratch (static device globals — no runtime allocation allowed)
__device__ float g_buf[NND * D];    // messages g = (A@W)*dis; reused as t3 in head
__device__ float acc_buf[NND * D];  // aggregated output per layer
__device__ float dis_buf[NND];
__device__ int   deg_buf[NND];      // in-degree WITHOUT self loop
__device__ int   scan_tmp[NND];
__device__ int   row_ptr[NND + 1];
__device__ int   cursor[NND];
__device__ int   csr_src[NE];
__device__ int   bsum[256];

// ---------------- f32x2 helpers ----------------

__device__ __forceinline__ u64 ffma2(u64 a, u64 b, u64 c) {
    u64 d;
    asm("fma.rn.f32x2 %0, %1, %2, %3;" : "=l"(d) : "l"(a), "l"(b), "l"(c));
    return d;
}
__device__ __forceinline__ u64 pack_dup(float x) {
    u64 r;
    asm("mov.b64 %0, {%1, %1};" : "=l"(r) : "f"(x));
    return r;
}
__device__ __forceinline__ float2 unpack2(u64 v) {
    float2 r;
    asm("mov.b64 {%0, %1}, %2;" : "=f"(r.x), "=f"(r.y) : "l"(v));
    return r;
}

// ---------------- degree / normalization / CSR build ----------------

__global__ void k_init_deg() {
    int i = blockIdx.x * blockDim.x + threadIdx.x;
    if (i < NND) deg_buf[i] = 0;
}

__global__ void k_count_deg(const int* __restrict__ dst) {
    int e = blockIdx.x * blockDim.x + threadIdx.x;
    if (e < NE) atomicAdd(&deg_buf[dst[e]], 1);
}

__global__ void k_dis() {
    int i = blockIdx.x * blockDim.x + threadIdx.x;
    if (i < NND) dis_buf[i] = rsqrtf((float)(deg_buf[i] + 1));
}

#define SCB 512
#define SCAN_BLOCKS ((NND + SCB - 1) / SCB)   // 196

__global__ __launch_bounds__(SCB) void k_scan1() {
    __shared__ int sm[SCB];
    int i = blockIdx.x * SCB + threadIdx.x;
    int v = (i < NND) ? deg_buf[i] : 0;
    sm[threadIdx.x] = v;
    __syncthreads();
#pragma unroll
    for (int off = 1; off < SCB; off <<= 1) {
        int t = (threadIdx.x >= off) ? sm[threadIdx.x - off] : 0;
        __syncthreads();
        sm[threadIdx.x] += t;
        __syncthreads();
    }
    if (i < NND) scan_tmp[i] = sm[threadIdx.x];
    if (threadIdx.x == SCB - 1) bsum[blockIdx.x] = sm[SCB - 1];
}

__global__ __launch_bounds__(256) void k_scan2() {
    __shared__ int sm[256];
    int v = (threadIdx.x < SCAN_BLOCKS) ? bsum[threadIdx.x] : 0;
    sm[threadIdx.x] = v;
    __syncthreads();
#pragma unroll
    for (int off = 1; off < 256; off <<= 1) {
        int t = (threadIdx.x >= off) ? sm[threadIdx.x - off] : 0;
        __syncthreads();
        sm[threadIdx.x] += t;
        __syncthreads();
    }
    bsum[threadIdx.x] = sm[threadIdx.x];  // inclusive
}

__global__ __launch_bounds__(SCB) void k_scan3() {
    int i = blockIdx.x * SCB + threadIdx.x;
    if (i >= NND) return;
    int off = (blockIdx.x > 0) ? bsum[blockIdx.x - 1] : 0;
    int inc = scan_tmp[i] + off;         // inclusive prefix sum of deg
    int st  = inc - deg_buf[i];
    row_ptr[i] = st;
    cursor[i]  = st;
    if (i == NND - 1) row_ptr[NND] = inc;
}

__global__ void k_fill(const int* __restrict__ src, const int* __restrict__ dst) {
    int e = blockIdx.x * blockDim.x + threadIdx.x;
    if (e >= NE) return;
    int p = atomicAdd(&cursor[dst[e]], 1);
    csr_src[p] = src[e];
}

// ---------------- GEMM: C[M,BN] = op_A(A)[M,128] @ W[128,BN] + epilogue ----------------
// BM=128 rows/block, 256 threads, thread tile TM x TN = 8 x TN (TN in {8,4}).
// N-paired f32x2 accumulation: each u64 acc holds 2 adjacent output columns.
// Thread column-pairs are STRIDED (pair p = tx + j*16) so w-fragment LDS.64s are
// lane-consecutive (conflict-free) and Ws smem is a verbatim copy of W's chunk.
//
// A_FUSE: A element = relu(rawA * dis[row] + biasA[col])   (fused GCN finalize)
// EPI 0: GCN  : C = acc * dis[row]          (messages g)
// EPI 1: BIAS : C = acc + biasC[col]
// EPI 2: LSM  : C = log_softmax(acc + biasC[col]) over row (BN=64)

template <int BN, int TN, bool A_FUSE, int EPI>
__global__ __launch_bounds__(256, 2)
void gemm_k128(const float* __restrict__ A,
               const float* __restrict__ W,
               const float* __restrict__ biasA,
               const float* __restrict__ biasC,
               const float* __restrict__ dis,
               float* __restrict__ C,
               int M)
{
    constexpr int BM = 128, K = 128, KC = 32, TM = 8;
    constexpr int TP  = TN / 2;           // u64 pairs per thread
    constexpr int SAP = KC + 4;           // As row stride (keeps float4 16B-aligned)
    __shared__ float As[BM * SAP];
    __shared__ u64   Ws2[KC * BN / 2];

    const int tid  = threadIdx.x;
    const int row0 = blockIdx.x * BM;
    const int tx   = tid & 15;
    const int ty   = tid >> 4;

    u64 acc[TM][TP];
#pragma unroll
    for (int i = 0; i < TM; i++)
#pragma unroll
        for (int j = 0; j < TP; j++) acc[i][j] = 0ULL;

    for (int kc = 0; kc < K; kc += KC) {
        // ---- load A chunk (BM x KC), optional fused finalize ----
#pragma unroll
        for (int p = 0; p < (BM * KC / 4) / 256; p++) {
            int i  = tid + p * 256;
            int r  = i / (KC / 4);
            int c4 = i % (KC / 4);
            float4 v = make_float4(0.f, 0.f, 0.f, 0.f);
            int row = row0 + r;
            if (row < M) {
                v = *(const float4*)(A + row * K + kc + c4 * 4);
                if (A_FUSE) {
                    float s = dis[row];
                    float4 b = *(const float4*)(biasA + kc + c4 * 4);
                    v.x = fmaxf(fmaf(v.x, s, b.x), 0.f);
                    v.y = fmaxf(fmaf(v.y, s, b.y), 0.f);
                    v.z = fmaxf(fmaf(v.z, s, b.z), 0.f);
                    v.w = fmaxf(fmaf(v.w, s, b.w), 0.f);
                }
            }
            *(float4*)(As + r * SAP + c4 * 4) = v;
        }
        // ---- load W chunk (KC x BN) verbatim ----
#pragma unroll
        for (int p = 0; p < (KC * BN / 4) / 256; p++) {
            int i = tid + p * 256;
            ((float4*)Ws2)[i] = *(const float4*)(W + kc * BN + i * 4);
        }
        __syncthreads();

        // ---- compute ----
#pragma unroll 8
        for (int k = 0; k < KC; k++) {
            u64 wp[TP];
#pragma unroll
            for (int j = 0; j < TP; j++)
                wp[j] = Ws2[k * (BN / 2) + j * 16 + tx];
            float a[TM];
#pragma unroll
            for (int i = 0; i < TM; i++)
                a[i] = As[(ty * TM + i) * SAP + k];
            u64 ap[TM];
#pragma unroll
            for (int i = 0; i < TM; i++) ap[i] = pack_dup(a[i]);
#pragma unroll
            for (int i = 0; i < TM; i++)
#pragma unroll
                for (int j = 0; j < TP; j++)
                    acc[i][j] = ffma2(ap[i], wp[j], acc[i][j]);
        }
        __syncthreads();
    }

    // ---------------- epilogue (column pair p=tx+j*16 -> cols 2p, 2p+1) ----------------
    if (EPI == 0) {
#pragma unroll
        for (int i = 0; i < TM; i++) {
            int row = row0 + ty * TM + i;
            if (row >= M) break;
            float s = dis[row];
#pragma unroll
            for (int j = 0; j < TP; j++) {
                float2 v = unpack2(acc[i][j]);
                v.x *= s; v.y *= s;
                *(float2*)(C + row * BN + 2 * (tx + j * 16)) = v;
            }
        }
    } else if (EPI == 1) {
#pragma unroll
        for (int i = 0; i < TM; i++) {
            int row = row0 + ty * TM + i;
            if (row >= M) break;
#pragma unroll
            for (int j = 0; j < TP; j++) {
                float2 b = *(const float2*)(biasC + 2 * (tx + j * 16));
                float2 v = unpack2(acc[i][j]);
                v.x += b.x; v.y += b.y;
                *(float2*)(C + row * BN + 2 * (tx + j * 16)) = v;
            }
        }
    } else {  // EPI 2: BN=64, TP=2, full row across 16 lanes
        float2 b0 = *(const float2*)(biasC + 2 * tx);
        float2 b1 = *(const float2*)(biasC + 2 * (tx + 16));
#pragma unroll
        for (int i = 0; i < TM; i++) {
            int row = row0 + ty * TM + i;
            float2 v0 = unpack2(acc[i][0]);
            float2 v1 = unpack2(acc[i][1]);
            float t0 = v0.x + b0.x, t1 = v0.y + b0.y;
            float t2 = v1.x + b1.x, t3 = v1.y + b1.y;
            float m = fmaxf(fmaxf(t0, t1), fmaxf(t2, t3));
#pragma unroll
            for (int o = 8; o; o >>= 1) m = fmaxf(m, __shfl_xor_sync(0xFFFFFFFFu, m, o));
            float s = expf(t0 - m) + expf(t1 - m) + expf(t2 - m) + expf(t3 - m);
#pragma unroll
            for (int o = 8; o; o >>= 1) s += __shfl_xor_sync(0xFFFFFFFFu, s, o);
            float l = m + logf(s);
            if (row < M) {
                float2 r0, r1;
                r0.x = t0 - l; r0.y = t1 - l;
                r1.x = t2 - l; r1.y = t3 - l;
                *(float2*)(C + row * BN + 2 * tx)        = r0;
                *(float2*)(C + row * BN + 2 * (tx + 16)) = r1;
            }
        }
    }
}

// ---------------- CSR gather: acc[v] = g[v] + sum_{e: dst=v} g[src[e]] ----------------

__global__ __launch_bounds__(256)
void k_gather(const float* __restrict__ g, float* __restrict__ acc)
{
    int node = (blockIdx.x * blockDim.x + threadIdx.x) >> 5;
    int lane = threadIdx.x & 31;
    if (node >= NND) return;
    int beg = row_ptr[node];
    int end = row_ptr[node + 1];
    const float4* gp = (const float4*)g;
    float4 a = gp[node * 32 + lane];  // self-loop term
    for (int e = beg; e < end; e++) {
        int s = __ldg(&csr_src[e]);   // warp-broadcast
        float4 v = gp[s * 32 + lane];
        a.x += v.x; a.y += v.y; a.z += v.z; a.w += v.w;
    }
    ((float4*)acc)[node * 32 + lane] = a;
}

// ---------------- launch ----------------

extern "C" void kernel_launch(void* const* d_in, const int* in_sizes, int n_in,
                              void* d_out, int out_size)
{
    const float* x   = (const float*)d_in[0];
    const int*   ei  = (const int*)d_in[1];
    const int*   src = ei;
    const int*   dst = ei + NE;
    const float* W1  = (const float*)d_in[2];
    const float* b1  = (const float*)d_in[3];
    const float* W2  = (const float*)d_in[4];
    const float* b2  = (const float*)d_in[5];
    const float* Wp1 = (const float*)d_in[6];
    const float* bp1 = (const float*)d_in[7];
    const float* Wp2 = (const float*)d_in[8];
    const float* bp2 = (const float*)d_in[9];
    float* out = (float*)d_out;

    float *g_p, *acc_p, *dis_p;
    cudaGetSymbolAddress((void**)&g_p,   g_buf);
    cudaGetSymbolAddress((void**)&acc_p, acc_buf);
    cudaGetSymbolAddress((void**)&dis_p, dis_buf);

    const int GEMM_BLOCKS   = (NND + 127) / 128;       // 782
    const int GATHER_BLOCKS = (NND * 32 + 255) / 256;  // 12500

    // ---- normalization + CSR build (overlaps nothing; all cheap) ----
    k_init_deg<<<(NND + 255) / 256, 256>>>();
    k_count_deg<<<(NE + 255) / 256, 256>>>(dst);
    k_dis<<<(NND + 255) / 256, 256>>>();
    k_scan1<<<SCAN_BLOCKS, SCB>>>();
    k_scan2<<<1, 256>>>();
    k_scan3<<<SCAN_BLOCKS, SCB>>>();
    k_fill<<<(NE + 255) / 256, 256>>>(src, dst);

    // ---- GCN layer 1: g = (x@W1)*dis ; acc = gather(g) ----
    gemm_k128<128, 8, false, 0><<<GEMM_BLOCKS, 256>>>(
        x, W1, nullptr, nullptr, dis_p, g_p, NND);
    k_gather<<<GATHER_BLOCKS, 256>>>(g_p, acc_p);

    // ---- GCN layer 2: A = relu(acc*dis + b1) fused; g = (A@W2)*dis ; gather ----
    gemm_k128<128, 8, true, 0><<<GEMM_BLOCKS, 256>>>(
        acc_p, W2, b1, nullptr, dis_p, g_p, NND);
    k_gather<<<GATHER_BLOCKS, 256>>>(g_p, acc_p);

    // ---- head 1: A = relu(acc*dis + b2) fused; t3 = A@Wp1 + bp1 ----
    gemm_k128<128, 8, true, 1><<<GEMM_BLOCKS, 256>>>(
        acc_p, Wp1, b2, bp1, dis_p, g_p, NND);

    // ---- head 2 + log_softmax: out = logsoftmax(t3@Wp2 + bp2) ----
    gemm_k128<64, 4, false, 2><<<GEMM_BLOCKS, 256>>>(
        g_p, Wp2, nullptr, bp2, nullptr, out, NND);
}

// round 5
// speedup vs baseline: 2.7959x; 1.2381x over previous
#include <cuda_runtime.h>
#include <math.h>

#define NND 100000
#define NE  1600000
#define D   128

typedef unsigned long long u64;

// Scratch (static device globals — no runtime allocation allowed)
__device__ float g_buf[NND * D];    // messages
__device__ float acc_buf[NND * D];  // aggregated output per layer
__device__ float dis_buf[NND];
__device__ int   deg_buf[NND];      // in-degree WITHOUT self loop
__device__ int   scan_tmp[NND];
__device__ int   row_ptr[NND + 1];
__device__ int   cursor[NND];
__device__ int   csr_src[NE];
__device__ int   bsum[256];
__device__ float Wf_buf[D * 64];    // fused head weight  Wp1@Wp2
__device__ float bF_buf[64];        // fused head bias    bp1@Wp2 + bp2

// ---------------- f32x2 helpers ----------------

__device__ __forceinline__ u64 ffma2(u64 a, u64 b, u64 c) {
    u64 d;
    asm("fma.rn.f32x2 %0, %1, %2, %3;" : "=l"(d) : "l"(a), "l"(b), "l"(c));
    return d;
}
__device__ __forceinline__ u64 pack_dup(float x) {
    u64 r;
    asm("mov.b64 %0, {%1, %1};" : "=l"(r) : "f"(x));
    return r;
}
__device__ __forceinline__ float2 unpack2(u64 v) {
    float2 r;
    asm("mov.b64 {%0, %1}, %2;" : "=f"(r.x), "=f"(r.y) : "l"(v));
    return r;
}

// ---------------- degree / normalization / CSR build ----------------

__global__ void k_init_deg() {
    int i = blockIdx.x * blockDim.x + threadIdx.x;
    if (i < NND) deg_buf[i] = 0;
}

__global__ void k_count_deg(const int* __restrict__ dst) {
    int e = blockIdx.x * blockDim.x + threadIdx.x;
    if (e < NE) atomicAdd(&deg_buf[dst[e]], 1);
}

__global__ void k_dis() {
    int i = blockIdx.x * blockDim.x + threadIdx.x;
    if (i < NND) dis_buf[i] = rsqrtf((float)(deg_buf[i] + 1));
}

#define SCB 512
#define SCAN_BLOCKS ((NND + SCB - 1) / SCB)   // 196

__global__ __launch_bounds__(SCB) void k_scan1() {
    __shared__ int sm[SCB];
    int i = blockIdx.x * SCB + threadIdx.x;
    int v = (i < NND) ? deg_buf[i] : 0;
    sm[threadIdx.x] = v;
    __syncthreads();
#pragma unroll
    for (int off = 1; off < SCB; off <<= 1) {
        int t = (threadIdx.x >= off) ? sm[threadIdx.x - off] : 0;
        __syncthreads();
        sm[threadIdx.x] += t;
        __syncthreads();
    }
    if (i < NND) scan_tmp[i] = sm[threadIdx.x];
    if (threadIdx.x == SCB - 1) bsum[blockIdx.x] = sm[SCB - 1];
}

__global__ __launch_bounds__(256) void k_scan2() {
    __shared__ int sm[256];
    int v = (threadIdx.x < SCAN_BLOCKS) ? bsum[threadIdx.x] : 0;
    sm[threadIdx.x] = v;
    __syncthreads();
#pragma unroll
    for (int off = 1; off < 256; off <<= 1) {
        int t = (threadIdx.x >= off) ? sm[threadIdx.x - off] : 0;
        __syncthreads();
        sm[threadIdx.x] += t;
        __syncthreads();
    }
    bsum[threadIdx.x] = sm[threadIdx.x];  // inclusive
}

__global__ __launch_bounds__(SCB) void k_scan3() {
    int i = blockIdx.x * SCB + threadIdx.x;
    if (i >= NND) return;
    int off = (blockIdx.x > 0) ? bsum[blockIdx.x - 1] : 0;
    int inc = scan_tmp[i] + off;
    int st  = inc - deg_buf[i];
    row_ptr[i] = st;
    cursor[i]  = st;
    if (i == NND - 1) row_ptr[NND] = inc;
}

__global__ void k_fill(const int* __restrict__ src, const int* __restrict__ dst) {
    int e = blockIdx.x * blockDim.x + threadIdx.x;
    if (e >= NE) return;
    int p = atomicAdd(&cursor[dst[e]], 1);
    csr_src[p] = src[e];
}

// ---------------- fused head weight precompute ----------------
// Wf[k][n] = sum_j Wp1[k][j] * Wp2[j][n];  bF[n] = sum_j bp1[j]*Wp2[j][n] + bp2[n]

__global__ __launch_bounds__(256) void k_fusew(const float* __restrict__ Wp1,
                                               const float* __restrict__ bp1,
                                               const float* __restrict__ Wp2,
                                               const float* __restrict__ bp2)
{
    int i = blockIdx.x * blockDim.x + threadIdx.x;  // 8192 threads
    if (i >= D * 64) return;
    int k = i >> 6, n = i & 63;
    float s = 0.0f;
#pragma unroll 8
    for (int j = 0; j < D; j++)
        s = fmaf(Wp1[k * D + j], Wp2[j * 64 + n], s);
    Wf_buf[i] = s;
    if (k == 0) {
        float t = bp2[n];
#pragma unroll 8
        for (int j = 0; j < D; j++)
            t = fmaf(bp1[j], Wp2[j * 64 + n], t);
        bF_buf[n] = t;
    }
}

// ---------------- GEMM: C[M,BN] = op_A(A)[M,128] @ W[128,BN] + epilogue ----------------
// BM=128 rows/block, 256 threads, thread tile 8 x TN, N-paired f32x2 accumulation.
// A_FUSE: A element = relu(rawA * dis[row] + biasA[col])
// EPI 0: C = acc * dis[row]
// EPI 2: C = log_softmax(acc + biasC[col]) over row (BN=64)
// EPI 3: C = acc  (plain)

template <int BN, int TN, bool A_FUSE, int EPI>
__global__ __launch_bounds__(256, 2)
void gemm_k128(const float* __restrict__ A,
               const float* __restrict__ W,
               const float* __restrict__ biasA,
               const float* __restrict__ biasC,
               const float* __restrict__ dis,
               float* __restrict__ C,
               int M)
{
    constexpr int BM = 128, K = 128, KC = 32, TM = 8;
    constexpr int TP  = TN / 2;
    constexpr int SAP = KC + 4;
    __shared__ float As[BM * SAP];
    __shared__ u64   Ws2[KC * BN / 2];

    const int tid  = threadIdx.x;
    const int row0 = blockIdx.x * BM;
    const int tx   = tid & 15;
    const int ty   = tid >> 4;

    u64 acc[TM][TP];
#pragma unroll
    for (int i = 0; i < TM; i++)
#pragma unroll
        for (int j = 0; j < TP; j++) acc[i][j] = 0ULL;

    for (int kc = 0; kc < K; kc += KC) {
#pragma unroll
        for (int p = 0; p < (BM * KC / 4) / 256; p++) {
            int i  = tid + p * 256;
            int r  = i / (KC / 4);
            int c4 = i % (KC / 4);
            float4 v = make_float4(0.f, 0.f, 0.f, 0.f);
            int row = row0 + r;
            if (row < M) {
                v = *(const float4*)(A + row * K + kc + c4 * 4);
                if (A_FUSE) {
                    float s = dis[row];
                    float4 b = *(const float4*)(biasA + kc + c4 * 4);
                    v.x = fmaxf(fmaf(v.x, s, b.x), 0.f);
                    v.y = fmaxf(fmaf(v.y, s, b.y), 0.f);
                    v.z = fmaxf(fmaf(v.z, s, b.z), 0.f);
                    v.w = fmaxf(fmaf(v.w, s, b.w), 0.f);
                }
            }
            *(float4*)(As + r * SAP + c4 * 4) = v;
        }
#pragma unroll
        for (int p = 0; p < (KC * BN / 4) / 256; p++) {
            int i = tid + p * 256;
            ((float4*)Ws2)[i] = *(const float4*)(W + kc * BN + i * 4);
        }
        __syncthreads();

#pragma unroll 8
        for (int k = 0; k < KC; k++) {
            u64 wp[TP];
#pragma unroll
            for (int j = 0; j < TP; j++)
                wp[j] = Ws2[k * (BN / 2) + j * 16 + tx];
            float a[TM];
#pragma unroll
            for (int i = 0; i < TM; i++)
                a[i] = As[(ty * TM + i) * SAP + k];
            u64 ap[TM];
#pragma unroll
            for (int i = 0; i < TM; i++) ap[i] = pack_dup(a[i]);
#pragma unroll
            for (int i = 0; i < TM; i++)
#pragma unroll
                for (int j = 0; j < TP; j++)
                    acc[i][j] = ffma2(ap[i], wp[j], acc[i][j]);
        }
        __syncthreads();
    }

    // ---------------- epilogue (column pair p=tx+j*16 -> cols 2p, 2p+1) ----------------
    if (EPI == 0 || EPI == 3) {
#pragma unroll
        for (int i = 0; i < TM; i++) {
            int row = row0 + ty * TM + i;
            if (row >= M) break;
            float s = (EPI == 0) ? dis[row] : 1.0f;
#pragma unroll
            for (int j = 0; j < TP; j++) {
                float2 v = unpack2(acc[i][j]);
                if (EPI == 0) { v.x *= s; v.y *= s; }
                *(float2*)(C + row * BN + 2 * (tx + j * 16)) = v;
            }
        }
    } else {  // EPI 2: BN=64, TP=2, full row across 16 lanes
        float2 b0 = *(const float2*)(biasC + 2 * tx);
        float2 b1 = *(const float2*)(biasC + 2 * (tx + 16));
#pragma unroll
        for (int i = 0; i < TM; i++) {
            int row = row0 + ty * TM + i;
            float2 v0 = unpack2(acc[i][0]);
            float2 v1 = unpack2(acc[i][1]);
            float t0 = v0.x + b0.x, t1 = v0.y + b0.y;
            float t2 = v1.x + b1.x, t3 = v1.y + b1.y;
            float m = fmaxf(fmaxf(t0, t1), fmaxf(t2, t3));
#pragma unroll
            for (int o = 8; o; o >>= 1) m = fmaxf(m, __shfl_xor_sync(0xFFFFFFFFu, m, o));
            float s = expf(t0 - m) + expf(t1 - m) + expf(t2 - m) + expf(t3 - m);
#pragma unroll
            for (int o = 8; o; o >>= 1) s += __shfl_xor_sync(0xFFFFFFFFu, s, o);
            float l = m + logf(s);
            if (row < M) {
                float2 r0, r1;
                r0.x = t0 - l; r0.y = t1 - l;
                r1.x = t2 - l; r1.y = t3 - l;
                *(float2*)(C + row * BN + 2 * tx)        = r0;
                *(float2*)(C + row * BN + 2 * (tx + 16)) = r1;
            }
        }
    }
}

// ---------------- CSR gather ----------------
// SCALE=1: acc[v] = dis[v]*g[v] + sum dis[s]*g[s]   (g unscaled; layer 1)
// SCALE=0: acc[v] = g[v]        + sum g[s]          (g pre-scaled;  layer 2)

template <bool SCALE>
__global__ __launch_bounds__(256)
void k_gather(const float* __restrict__ g, const float* __restrict__ dis,
              float* __restrict__ acc)
{
    int node = (blockIdx.x * blockDim.x + threadIdx.x) >> 5;
    int lane = threadIdx.x & 31;
    if (node >= NND) return;
    int beg = row_ptr[node];
    int end = row_ptr[node + 1];
    const float4* gp = (const float4*)g;
    float4 a = gp[node * 32 + lane];  // self-loop term
    if (SCALE) {
        float dv = dis[node];
        a.x *= dv; a.y *= dv; a.z *= dv; a.w *= dv;
    }
    for (int e = beg; e < end; e++) {
        int s = __ldg(&csr_src[e]);
        float4 v = gp[s * 32 + lane];
        if (SCALE) {
            float ds = __ldg(&dis[s]);
            a.x = fmaf(v.x, ds, a.x); a.y = fmaf(v.y, ds, a.y);
            a.z = fmaf(v.z, ds, a.z); a.w = fmaf(v.w, ds, a.w);
        } else {
            a.x += v.x; a.y += v.y; a.z += v.z; a.w += v.w;
        }
    }
    ((float4*)acc)[node * 32 + lane] = a;
}

// ---------------- launch ----------------

extern "C" void kernel_launch(void* const* d_in, const int* in_sizes, int n_in,
                              void* d_out, int out_size)
{
    const float* x   = (const float*)d_in[0];
    const int*   ei  = (const int*)d_in[1];
    const int*   src = ei;
    const int*   dst = ei + NE;
    const float* W1  = (const float*)d_in[2];
    const float* b1  = (const float*)d_in[3];
    const float* W2  = (const float*)d_in[4];
    const float* b2  = (const float*)d_in[5];
    const float* Wp1 = (const float*)d_in[6];
    const float* bp1 = (const float*)d_in[7];
    const float* Wp2 = (const float*)d_in[8];
    const float* bp2 = (const float*)d_in[9];
    float* out = (float*)d_out;

    float *g_p, *acc_p, *dis_p, *wf_p, *bf_p;
    cudaGetSymbolAddress((void**)&g_p,   g_buf);
    cudaGetSymbolAddress((void**)&acc_p, acc_buf);
    cudaGetSymbolAddress((void**)&dis_p, dis_buf);
    cudaGetSymbolAddress((void**)&wf_p,  Wf_buf);
    cudaGetSymbolAddress((void**)&bf_p,  bF_buf);

    // side stream + fork/join events, created once (outside any graph capture)
    static cudaStream_t s2 = nullptr;
    static cudaEvent_t  ev_fork = nullptr, ev_join = nullptr;
    if (!s2) {
        cudaStreamCreateWithFlags(&s2, cudaStreamNonBlocking);
        cudaEventCreateWithFlags(&ev_fork, cudaEventDisableTiming);
        cudaEventCreateWithFlags(&ev_join, cudaEventDisableTiming);
    }

    const int GEMM_BLOCKS   = (NND + 127) / 128;       // 782
    const int GATHER_BLOCKS = (NND * 32 + 255) / 256;  // 12500

    // ---- fork: CSR build + norm + head-weight fusion on s2, GEMM1 on main ----
    cudaEventRecord(ev_fork, 0);
    cudaStreamWaitEvent(s2, ev_fork, 0);

    k_fusew<<<(D * 64 + 255) / 256, 256, 0, s2>>>(Wp1, bp1, Wp2, bp2);
    k_init_deg<<<(NND + 255) / 256, 256, 0, s2>>>();
    k_count_deg<<<(NE + 255) / 256, 256, 0, s2>>>(dst);
    k_dis<<<(NND + 255) / 256, 256, 0, s2>>>();
    k_scan1<<<SCAN_BLOCKS, SCB, 0, s2>>>();
    k_scan2<<<1, 256, 0, s2>>>();
    k_scan3<<<SCAN_BLOCKS, SCB, 0, s2>>>();
    k_fill<<<(NE + 255) / 256, 256, 0, s2>>>(src, dst);
    cudaEventRecord(ev_join, s2);

    // GEMM1 (no dis dependency): g = x@W1  (plain)
    gemm_k128<128, 8, false, 3><<<GEMM_BLOCKS, 256>>>(
        x, W1, nullptr, nullptr, nullptr, g_p, NND);

    cudaStreamWaitEvent(0, ev_join, 0);

    // ---- layer 1 aggregate (scaled gather) ----
    k_gather<true><<<GATHER_BLOCKS, 256>>>(g_p, dis_p, acc_p);

    // ---- GCN layer 2: A = relu(acc*dis + b1) fused; g = (A@W2)*dis ; gather ----
    gemm_k128<128, 8, true, 0><<<GEMM_BLOCKS, 256>>>(
        acc_p, W2, b1, nullptr, dis_p, g_p, NND);
    k_gather<false><<<GATHER_BLOCKS, 256>>>(g_p, dis_p, acc_p);

    // ---- fused head + log_softmax: out = logsoftmax(relu(acc*dis+b2) @ Wf + bF) ----
    gemm_k128<64, 4, true, 2><<<GEMM_BLOCKS, 256>>>(
        acc_p, wf_p, b2, bf_p, dis_p, out, NND);
}